// round 14
// baseline (speedup 1.0000x reference)
#include <cuda_runtime.h>
#include <math.h>
#include <stdint.h>

// Problem constants
#define T_DIM 2048
#define B_DIM 1024
#define A_DIM 4
#define D_DIM 128

constexpr int THREADS = 512;
constexpr int CHUNK   = 32;               // timesteps per tile -> 128 GEMM rows
constexpr int NCHUNK  = T_DIM / CHUNK;    // 64
constexpr int SROW    = 136;              // padded row stride (floats)

// Output layout: [logits (T,1,B,A)] [q (B,A,D)] [h (B,A,D)]
constexpr int OUT_Q = T_DIM * B_DIM * A_DIM;
constexpr int OUT_H = OUT_Q + B_DIM * A_DIM * D_DIM;

// SMEM layout (float offsets)
constexpr int SM_B      = 0;                    // C^T tf32, PAIR-PERMUTED cols
constexpr int SM_A      = SM_B + 128 * SROW;    // H tile, PAIR-PERMUTED cols, tf32 bits
constexpr int SM_Q      = SM_A + 128 * SROW;    // Q tile, logical cols, fp32
constexpr int SM_PHI    = SM_Q + 128 * SROW;
constexpr int SM_OMPHI  = SM_PHI + 128;
constexpr int SM_CHI    = SM_OMPHI + 128;
constexpr int SM_OMCHI  = SM_CHI + 128;
constexpr int SM_BETA   = SM_OMCHI + 128;       // logical order (epilogue)
constexpr int SM_KAPPAP = SM_BETA + 128;        // PAIR-PERMUTED order (kappa.h)
constexpr int SM_INP    = SM_KAPPAP + 128;      // 32 t x 8
constexpr int SM_PART   = SM_INP + 256;         // 4 col-groups x 128 rows
constexpr int SM_KH     = SM_PART + 512;        // 128
constexpr int SM_TOT    = SM_KH + 128;          // 53888 floats
constexpr int SMEM_BYTES = SM_TOT * 4;          // 215,552 B

// pair permutation: logical col c -> slot (c&~7) + (2*(c&3) + ((c>>2)&1))
// maps (k*8+qd, k*8+qd+4) -> adjacent slots (k*8+2qd, k*8+2qd+1)
__device__ __host__ __forceinline__ int pslot(int c) {
    return (c & ~7) + (((c & 3) << 1) | ((c >> 2) & 1));
}

__device__ __forceinline__ uint32_t f2tf(float x) {
    uint32_t u;
    asm("cvt.rna.tf32.f32 %0, %1;" : "=r"(u) : "f"(x));
    return u;
}

__device__ __forceinline__ void mma_tf32(float* c, const uint32_t* a, const uint32_t* b) {
    asm volatile(
        "mma.sync.aligned.m16n8k8.row.col.f32.tf32.tf32.f32 "
        "{%0,%1,%2,%3}, {%4,%5,%6,%7}, {%8,%9}, {%0,%1,%2,%3};\n"
        : "+f"(c[0]), "+f"(c[1]), "+f"(c[2]), "+f"(c[3])
        : "r"(a[0]), "r"(a[1]), "r"(a[2]), "r"(a[3]),
          "r"(b[0]), "r"(b[1]));
}

__global__ __launch_bounds__(THREADS, 1)
void gql_kernel(const float* __restrict__ inp,       // (T,1,B,9)
                const float* __restrict__ phi_raw,   // (P,D)
                const float* __restrict__ chi_raw,
                const float* __restrict__ beta_raw,
                const float* __restrict__ kap_raw,
                const float* __restrict__ C_raw,     // (P,D,D)
                float* __restrict__ out)
{
    extern __shared__ float sm[];
    const int b    = blockIdx.x;
    const int tid  = threadIdx.x;
    const int lane = tid & 31;
    const int warp = tid >> 5;

    const int pid = (int)inp[b * 9 + 8];

    // ---------------- one-time parameter setup ----------------
    if (tid < 128) {
        const int d = tid;
        float pv = phi_raw[pid * 128 + d];
        float ph = 1.0f / (1.0f + expf(-pv));
        ph = fminf(fmaxf(ph, 0.01f), 0.99f);
        sm[SM_PHI + d]   = ph;
        sm[SM_OMPHI + d] = 1.0f - ph;

        float cv = chi_raw[pid * 128 + d];
        float ch = 1.0f / (1.0f + expf(-cv));
        ch = fminf(fmaxf(ch, 0.01f), 0.99f);
        sm[SM_CHI + d]   = ch;
        sm[SM_OMCHI + d] = 1.0f - ch;

        float bv = beta_raw[pid * 128 + d];
        float sp = (bv > 15.0f) ? bv : log1pf(expf(bv));
        sm[SM_BETA + d] = fminf(fmaxf(sp, 0.1f), 10.0f);

        float kv = kap_raw[pid * 128 + d];
        sm[SM_KAPPAP + pslot(d)] = fminf(fmaxf(kv, -10.0f), 10.0f);
    }

    // C[pid]: clip, tf32-round, transposed + pair-permuted k columns
    {
        const float* Cb = C_raw + (size_t)pid * (128 * 128);
        for (int i = tid; i < 128 * 128; i += THREADS) {
            int d = i >> 7, e = i & 127;
            float v = fminf(fmaxf(Cb[i], -10.0f), 10.0f);
            sm[SM_B + e * SROW + pslot(d)] = __uint_as_float(f2tf(v));
        }
    }
    __syncthreads();

    // warp grid 4x4, warp tile: 32 rows x 32 cols
    const int wm  = warp >> 2;   // 0..3
    const int wn  = warp & 3;    // 0..3
    const int grp = lane >> 2;   // 0..7
    const int qd  = lane & 3;    // 0..3

    // ---- hoist B fragments for K-steps 0..3 only (32 regs) ----
    uint32_t bf[4][4][2];
#pragma unroll
    for (int k = 0; k < 4; k++) {
#pragma unroll
        for (int j = 0; j < 4; j++) {
            float2 v = *(const float2*)&sm[SM_B + (wn * 32 + j * 8 + grp) * SROW + k * 8 + qd * 2];
            bf[k][j][0] = __float_as_uint(v.x);
            bf[k][j][1] = __float_as_uint(v.y);
        }
    }

    // ---------------- per-thread scan state: one (a,d) element ----------------
    const int a_own = tid >> 7;       // constant within warp
    const int d_own = tid & 127;
    const int slotd = pslot(d_own);

    const float phi = sm[SM_PHI + d_own],   omp = sm[SM_OMPHI + d_own];
    const float chi = sm[SM_CHI + d_own],   omc = sm[SM_OMCHI + d_own];

    float q = 0.5f, h = 0.0f;

    for (int c = 0; c < NCHUNK; c++) {
        const int tb = c * CHUNK;

        // ---- stage 1: load chunk inputs ----
        if (tid < 256) {
            int t = tid >> 3, cc = tid & 7;
            float v = inp[((size_t)(tb + t) * B_DIM + b) * 9 + cc];
            if (v != v) v = 0.0f;   // nan_to_num
            sm[SM_INP + tid] = v;
        }
        __syncthreads();

        // ---- stage 2: EMA scan -> H (tf32, permuted) + Q (fp32, logical) ----
#pragma unroll 8
        for (int t = 0; t < CHUNK; t++) {
            float av = sm[SM_INP + t * 8 + a_own];
            float rv = sm[SM_INP + t * 8 + 4 + a_own];
            q = fmaf(phi, rv * av, omp * q);
            h = fmaf(chi, av, omc * h);
            int row = t * 4 + a_own;
            sm[SM_A + row * SROW + slotd] = __uint_as_float(f2tf(h));
            sm[SM_Q + row * SROW + d_own] = q;
        }
        __syncthreads();

        // ---- stage 3: P = H * C (tf32 mma), warp tile 32x32 ----
        float acc[2][4][4];
#pragma unroll
        for (int i = 0; i < 2; i++)
#pragma unroll
            for (int j = 0; j < 4; j++)
#pragma unroll
                for (int r = 0; r < 4; r++) acc[i][j][r] = 0.0f;

#pragma unroll
        for (int k = 0; k < 16; k++) {
            uint32_t af[2][4];
#pragma unroll
            for (int i = 0; i < 2; i++) {
                const int r0 = wm * 32 + i * 16 + grp;
                float2 v0 = *(const float2*)&sm[SM_A + r0 * SROW + k * 8 + qd * 2];
                float2 v1 = *(const float2*)&sm[SM_A + (r0 + 8) * SROW + k * 8 + qd * 2];
                af[i][0] = __float_as_uint(v0.x);
                af[i][1] = __float_as_uint(v1.x);
                af[i][2] = __float_as_uint(v0.y);
                af[i][3] = __float_as_uint(v1.y);
            }
            if (k < 4) {
#pragma unroll
                for (int i = 0; i < 2; i++)
#pragma unroll
                    for (int j = 0; j < 4; j++)
                        mma_tf32(acc[i][j], af[i], bf[k][j]);
            } else {
                uint32_t bt[4][2];
#pragma unroll
                for (int j = 0; j < 4; j++) {
                    float2 v = *(const float2*)&sm[SM_B + (wn * 32 + j * 8 + grp) * SROW + k * 8 + qd * 2];
                    bt[j][0] = __float_as_uint(v.x);
                    bt[j][1] = __float_as_uint(v.y);
                }
#pragma unroll
                for (int i = 0; i < 2; i++)
#pragma unroll
                    for (int j = 0; j < 4; j++)
                        mma_tf32(acc[i][j], af[i], bt[j]);
            }
        }

        // ---- kappa . h (permuted order; dot order-invariant) ----
        {
            int row = tid >> 2, seg = tid & 3;
            float kh = 0.0f;
            const float4* hv = (const float4*)&sm[SM_A + row * SROW + seg * 32];
            const float4* kv = (const float4*)&sm[SM_KAPPAP + seg * 32];
#pragma unroll
            for (int d = 0; d < 8; d++) {
                float4 hh = hv[d], kk = kv[d];
                kh += hh.x * kk.x + hh.y * kk.y + hh.z * kk.z + hh.w * kk.w;
            }
            kh += __shfl_xor_sync(0xFFFFFFFFu, kh, 1);
            kh += __shfl_xor_sync(0xFFFFFFFFu, kh, 2);
            if (seg == 0) sm[SM_KH + row] = kh;
        }

        // ---- epilogue: rowdot((P + beta^T), Q) -> PART[wn][row] ----
#pragma unroll
        for (int i = 0; i < 2; i++) {
            float part0 = 0.0f, part1 = 0.0f;
            const int r0 = wm * 32 + i * 16 + grp;
            const int r1 = r0 + 8;
#pragma unroll
            for (int j = 0; j < 4; j++) {
                const int col = wn * 32 + j * 8 + qd * 2;
                const float b0 = sm[SM_BETA + col];
                const float b1 = sm[SM_BETA + col + 1];
                float2 qv0 = *(const float2*)&sm[SM_Q + r0 * SROW + col];
                float2 qv1 = *(const float2*)&sm[SM_Q + r1 * SROW + col];
                part0 += (acc[i][j][0] + b0) * qv0.x + (acc[i][j][1] + b1) * qv0.y;
                part1 += (acc[i][j][2] + b0) * qv1.x + (acc[i][j][3] + b1) * qv1.y;
            }
            part0 += __shfl_xor_sync(0xFFFFFFFFu, part0, 1);
            part0 += __shfl_xor_sync(0xFFFFFFFFu, part0, 2);
            part1 += __shfl_xor_sync(0xFFFFFFFFu, part1, 1);
            part1 += __shfl_xor_sync(0xFFFFFFFFu, part1, 2);
            if (qd == 0) {
                sm[SM_PART + wn * 128 + r0] = part0;
                sm[SM_PART + wn * 128 + r1] = part1;
            }
        }
        __syncthreads();

        // ---- stage 5: combine col-groups + kappa.h, write logits (T,1,B,A) ----
        if (tid < 128) {
            float l = sm[SM_PART + tid] + sm[SM_PART + 128 + tid]
                    + sm[SM_PART + 256 + tid] + sm[SM_PART + 384 + tid]
                    + sm[SM_KH + tid];
            int t = tb + (tid >> 2);
            int a = tid & 3;
            out[(size_t)t * (B_DIM * A_DIM) + b * A_DIM + a] = l;
        }
        __syncthreads();
    }

    // ---- final states: q (B,A,D) then h (B,A,D) ----
    out[OUT_Q + (size_t)b * 512 + a_own * 128 + d_own] = q;
    out[OUT_H + (size_t)b * 512 + a_own * 128 + d_own] = h;
}

extern "C" void kernel_launch(void* const* d_in, const int* in_sizes, int n_in,
                              void* d_out, int out_size) {
    const float* inp      = (const float*)d_in[0];
    const float* phi_raw  = (const float*)d_in[1];
    const float* chi_raw  = (const float*)d_in[2];
    const float* beta_raw = (const float*)d_in[3];
    const float* kap_raw  = (const float*)d_in[4];
    const float* C_raw    = (const float*)d_in[5];
    float* out = (float*)d_out;

    cudaFuncSetAttribute(gql_kernel, cudaFuncAttributeMaxDynamicSharedMemorySize, SMEM_BYTES);
    gql_kernel<<<B_DIM, THREADS, SMEM_BYTES>>>(inp, phi_raw, chi_raw, beta_raw,
                                               kap_raw, C_raw, out);
}

// round 16
// speedup vs baseline: 1.7184x; 1.7184x over previous
#include <cuda_runtime.h>
#include <cuda_bf16.h>
#include <math.h>
#include <stdint.h>

// Problem constants
#define T_DIM 2048
#define B_DIM 1024
#define A_DIM 4
#define D_DIM 128

constexpr int THREADS = 256;
constexpr int CHUNK   = 32;               // timesteps per tile -> 128 GEMM rows
constexpr int NCHUNK  = T_DIM / CHUNK;    // 64
constexpr int HROW    = 68;               // H/B tile row stride in u32 (64 data + 4 pad)
constexpr int QROW    = 132;              // Q tile row stride in floats

// Output layout: [logits (T,1,B,A)] [q (B,A,D)] [h (B,A,D)]
constexpr int OUT_Q = T_DIM * B_DIM * A_DIM;
constexpr int OUT_H = OUT_Q + B_DIM * A_DIM * D_DIM;

// SMEM layout (4-byte word offsets)
constexpr int SM_BH    = 0;                    // C (K=d x N=e) bf16x2 pairs: row e, 64 u32
constexpr int SM_AH    = SM_BH + 128 * HROW;   // H tile bf16x2 pairs: row r, 64 u32
constexpr int SM_Q     = SM_AH + 128 * HROW;   // Q tile fp32 logical
constexpr int SM_PHI   = SM_Q + 128 * QROW;
constexpr int SM_OMPHI = SM_PHI + 128;
constexpr int SM_CHI   = SM_OMPHI + 128;
constexpr int SM_OMCHI = SM_CHI + 128;
constexpr int SM_BETA  = SM_OMCHI + 128;
constexpr int SM_KAPPA = SM_BETA + 128;
constexpr int SM_INP   = SM_KAPPA + 128;       // 32 t x 8
constexpr int SM_PART  = SM_INP + 256;         // 4 col-groups x 128 rows
constexpr int SM_KH    = SM_PART + 512;        // 128
constexpr int SM_TOT   = SM_KH + 128;          // 35968 words
constexpr int SMEM_BYTES = SM_TOT * 4;         // 143,872 B

__device__ __forceinline__ void mma_bf16(float* c, const uint32_t* a, const uint32_t* b) {
    asm volatile(
        "mma.sync.aligned.m16n8k16.row.col.f32.bf16.bf16.f32 "
        "{%0,%1,%2,%3}, {%4,%5,%6,%7}, {%8,%9}, {%0,%1,%2,%3};\n"
        : "+f"(c[0]), "+f"(c[1]), "+f"(c[2]), "+f"(c[3])
        : "r"(a[0]), "r"(a[1]), "r"(a[2]), "r"(a[3]),
          "r"(b[0]), "r"(b[1]));
}

__device__ __forceinline__ uint32_t pack_bf2(float x, float y) {
    __nv_bfloat162 p = __floats2bfloat162_rn(x, y);
    return *(uint32_t*)&p;
}

__global__ __launch_bounds__(THREADS, 1)
void gql_kernel(const float* __restrict__ inp,       // (T,1,B,9)
                const float* __restrict__ phi_raw,   // (P,D)
                const float* __restrict__ chi_raw,
                const float* __restrict__ beta_raw,
                const float* __restrict__ kap_raw,
                const float* __restrict__ C_raw,     // (P,D,D)
                float* __restrict__ out)
{
    extern __shared__ float sm[];
    uint32_t* smu = (uint32_t*)sm;
    const int b    = blockIdx.x;
    const int tid  = threadIdx.x;
    const int lane = tid & 31;
    const int warp = tid >> 5;

    const int pid = (int)inp[b * 9 + 8];

    // ---------------- one-time parameter setup ----------------
    if (tid < 128) {
        const int d = tid;
        float pv = phi_raw[pid * 128 + d];
        float ph = 1.0f / (1.0f + expf(-pv));
        ph = fminf(fmaxf(ph, 0.01f), 0.99f);
        sm[SM_PHI + d]   = ph;
        sm[SM_OMPHI + d] = 1.0f - ph;

        float cv = chi_raw[pid * 128 + d];
        float ch = 1.0f / (1.0f + expf(-cv));
        ch = fminf(fmaxf(ch, 0.01f), 0.99f);
        sm[SM_CHI + d]   = ch;
        sm[SM_OMCHI + d] = 1.0f - ch;

        float bv = beta_raw[pid * 128 + d];
        float sp = (bv > 15.0f) ? bv : log1pf(expf(bv));
        sm[SM_BETA + d] = fminf(fmaxf(sp, 0.1f), 10.0f);

        float kv = kap_raw[pid * 128 + d];
        sm[SM_KAPPA + d] = fminf(fmaxf(kv, -10.0f), 10.0f);
    }

    // C[pid]: clip, pack k-pairs (d, d+1) as bf16x2; smem row = e, u32 col = d/2
    {
        const float* Cb = C_raw + (size_t)pid * (128 * 128);
        for (int idx = tid; idx < 64 * 128; idx += THREADS) {
            int e  = idx & 127;
            int dp = idx >> 7;            // 0..63
            float v0 = fminf(fmaxf(Cb[(2 * dp)     * 128 + e], -10.0f), 10.0f);
            float v1 = fminf(fmaxf(Cb[(2 * dp + 1) * 128 + e], -10.0f), 10.0f);
            smu[SM_BH + e * HROW + dp] = pack_bf2(v0, v1);
        }
    }
    __syncthreads();

    // warp tile: 64 rows x 32 cols. wm in {0,1}, wn in {0..3}
    const int wm  = warp >> 2;
    const int wn  = warp & 3;
    const int grp = lane >> 2;   // 0..7
    const int qd  = lane & 3;    // 0..3

    // ---- hoist B fragments (C) into registers: 8 K16-steps x 4 j x 2 regs ----
    uint32_t bf[8][4][2];
#pragma unroll
    for (int k = 0; k < 8; k++) {
#pragma unroll
        for (int j = 0; j < 4; j++) {
            const uint32_t* base = &smu[SM_BH + (wn * 32 + j * 8 + grp) * HROW + k * 8 + qd];
            bf[k][j][0] = base[0];    // k16 rows 2qd, 2qd+1
            bf[k][j][1] = base[4];    // k16 rows 2qd+8, 2qd+9
        }
    }

    // ---------------- per-thread scan state: owns (a, d0) and (a, d0+1) ----
    const int e0    = tid * 2;
    const int a_own = e0 >> 7;
    const int d0    = e0 & 127;

    const float phi0 = sm[SM_PHI + d0],   phi1 = sm[SM_PHI + d0 + 1];
    const float omp0 = sm[SM_OMPHI + d0], omp1 = sm[SM_OMPHI + d0 + 1];
    const float chi0 = sm[SM_CHI + d0],   chi1 = sm[SM_CHI + d0 + 1];
    const float omc0 = sm[SM_OMCHI + d0], omc1 = sm[SM_OMCHI + d0 + 1];

    float q0 = 0.5f, q1 = 0.5f, h0 = 0.0f, h1 = 0.0f;

    for (int c = 0; c < NCHUNK; c++) {
        const int tb = c * CHUNK;

        // ---- stage 1: load chunk inputs ----
        {
            int t = tid >> 3, cc = tid & 7;
            float v = inp[((size_t)(tb + t) * B_DIM + b) * 9 + cc];
            if (v != v) v = 0.0f;   // nan_to_num
            sm[SM_INP + tid] = v;
        }
        __syncthreads();

        // ---- stage 2: EMA scan -> H (bf16x2) + Q (fp32) tiles ----
#pragma unroll 8
        for (int t = 0; t < CHUNK; t++) {
            float av = sm[SM_INP + t * 8 + a_own];
            float rv = sm[SM_INP + t * 8 + 4 + a_own];
            float drive = rv * av;
            q0 = fmaf(phi0, drive, omp0 * q0);
            q1 = fmaf(phi1, drive, omp1 * q1);
            h0 = fmaf(chi0, av, omc0 * h0);
            h1 = fmaf(chi1, av, omc1 * h1);
            int row = t * 4 + a_own;
            smu[SM_AH + row * HROW + (d0 >> 1)] = pack_bf2(h0, h1);
            *(float2*)&sm[SM_Q + row * QROW + d0] = make_float2(q0, q1);
        }
        __syncthreads();

        // ---- stage 3: P = H * C (bf16 m16n8k16), warp tile 64x32 ----
        float acc[4][4][4];
#pragma unroll
        for (int i = 0; i < 4; i++)
#pragma unroll
            for (int j = 0; j < 4; j++)
#pragma unroll
                for (int r = 0; r < 4; r++) acc[i][j][r] = 0.0f;

#pragma unroll
        for (int k = 0; k < 8; k++) {
            uint32_t af[4][4];
#pragma unroll
            for (int i = 0; i < 4; i++) {
                const int r0 = wm * 64 + i * 16 + grp;
                const uint32_t* b0 = &smu[SM_AH + r0 * HROW + k * 8 + qd];
                const uint32_t* b1 = &smu[SM_AH + (r0 + 8) * HROW + k * 8 + qd];
                af[i][0] = b0[0];    // (grp,   k16 cols 2qd..2qd+1)
                af[i][1] = b1[0];    // (grp+8, same)
                af[i][2] = b0[4];    // (grp,   k16 cols 2qd+8..9)
                af[i][3] = b1[4];    // (grp+8, same)
            }
#pragma unroll
            for (int i = 0; i < 4; i++)
#pragma unroll
                for (int j = 0; j < 4; j++)
                    mma_bf16(acc[i][j], af[i], bf[k][j]);
        }

        // ---- kappa . h (bf16 H, fp32 kappa + accumulate) ----
        if (tid < 128) {
            float kh = 0.0f;
            const uint4* hv = (const uint4*)&smu[SM_AH + tid * HROW];
            const float4* kv = (const float4*)&sm[SM_KAPPA];
#pragma unroll
            for (int m = 0; m < 16; m++) {
                uint4 w = hv[m];
                float2 p0 = __bfloat1622float2(*(__nv_bfloat162*)&w.x);
                float2 p1 = __bfloat1622float2(*(__nv_bfloat162*)&w.y);
                float2 p2 = __bfloat1622float2(*(__nv_bfloat162*)&w.z);
                float2 p3 = __bfloat1622float2(*(__nv_bfloat162*)&w.w);
                float4 k0 = kv[2 * m], k1 = kv[2 * m + 1];
                kh += p0.x * k0.x + p0.y * k0.y + p1.x * k0.z + p1.y * k0.w
                    + p2.x * k1.x + p2.y * k1.y + p3.x * k1.z + p3.y * k1.w;
            }
            sm[SM_KH + tid] = kh;
        }

        // ---- epilogue: rowdot((P + beta^T), Q) -> PART[wn][row] ----
#pragma unroll
        for (int i = 0; i < 4; i++) {
            float part0 = 0.0f, part1 = 0.0f;
            const int r0 = wm * 64 + i * 16 + grp;
            const int r1 = r0 + 8;
#pragma unroll
            for (int j = 0; j < 4; j++) {
                const int col = wn * 32 + j * 8 + qd * 2;
                const float b0 = sm[SM_BETA + col];
                const float b1 = sm[SM_BETA + col + 1];
                float2 qv0 = *(const float2*)&sm[SM_Q + r0 * QROW + col];
                float2 qv1 = *(const float2*)&sm[SM_Q + r1 * QROW + col];
                part0 += (acc[i][j][0] + b0) * qv0.x + (acc[i][j][1] + b1) * qv0.y;
                part1 += (acc[i][j][2] + b0) * qv1.x + (acc[i][j][3] + b1) * qv1.y;
            }
            part0 += __shfl_xor_sync(0xFFFFFFFFu, part0, 1);
            part0 += __shfl_xor_sync(0xFFFFFFFFu, part0, 2);
            part1 += __shfl_xor_sync(0xFFFFFFFFu, part1, 1);
            part1 += __shfl_xor_sync(0xFFFFFFFFu, part1, 2);
            if (qd == 0) {
                sm[SM_PART + wn * 128 + r0] = part0;
                sm[SM_PART + wn * 128 + r1] = part1;
            }
        }
        __syncthreads();

        // ---- stage 5: combine col-groups + kappa.h, write logits (T,1,B,A) ----
        if (tid < 128) {
            float l = sm[SM_PART + tid] + sm[SM_PART + 128 + tid]
                    + sm[SM_PART + 256 + tid] + sm[SM_PART + 384 + tid]
                    + sm[SM_KH + tid];
            int t = tb + (tid >> 2);
            int a = tid & 3;
            out[(size_t)t * (B_DIM * A_DIM) + b * A_DIM + a] = l;
        }
        __syncthreads();
    }

    // ---- final states: q (B,A,D) then h (B,A,D), exact fp32 ----
    *(float2*)&out[OUT_Q + (size_t)b * 512 + e0] = make_float2(q0, q1);
    *(float2*)&out[OUT_H + (size_t)b * 512 + e0] = make_float2(h0, h1);
}

extern "C" void kernel_launch(void* const* d_in, const int* in_sizes, int n_in,
                              void* d_out, int out_size) {
    const float* inp      = (const float*)d_in[0];
    const float* phi_raw  = (const float*)d_in[1];
    const float* chi_raw  = (const float*)d_in[2];
    const float* beta_raw = (const float*)d_in[3];
    const float* kap_raw  = (const float*)d_in[4];
    const float* C_raw    = (const float*)d_in[5];
    float* out = (float*)d_out;

    cudaFuncSetAttribute(gql_kernel, cudaFuncAttributeMaxDynamicSharedMemorySize, SMEM_BYTES);
    gql_kernel<<<B_DIM, THREADS, SMEM_BYTES>>>(inp, phi_raw, chi_raw, beta_raw,
                                               kap_raw, C_raw, out);
}

// round 17
// speedup vs baseline: 1.9884x; 1.1572x over previous
#include <cuda_runtime.h>
#include <cuda_bf16.h>
#include <math.h>
#include <stdint.h>

// Problem constants
#define T_DIM 2048
#define B_DIM 1024
#define A_DIM 4
#define D_DIM 128

constexpr int THREADS = 256;
constexpr int CHUNK   = 16;               // timesteps per tile -> 64 GEMM rows
constexpr int NCHUNK  = T_DIM / CHUNK;    // 128
constexpr int ROWS    = CHUNK * A_DIM;    // 64
constexpr int HROW    = 68;               // H/B tile row stride in u32 (64 data + 4 pad)
constexpr int QROW    = 132;              // Q tile row stride in floats

// Output layout: [logits (T,1,B,A)] [q (B,A,D)] [h (B,A,D)]
constexpr int OUT_Q = T_DIM * B_DIM * A_DIM;
constexpr int OUT_H = OUT_Q + B_DIM * A_DIM * D_DIM;

// SMEM layout (4-byte word offsets)
constexpr int SM_BH    = 0;                     // C (K=d x N=e) bf16x2: row e, 64 u32
constexpr int SM_AH    = SM_BH + 128 * HROW;    // H tile bf16x2: row r (64), 64 u32
constexpr int SM_Q     = SM_AH + ROWS * HROW;   // Q tile fp32 (64 rows)
constexpr int SM_PHI   = SM_Q + ROWS * QROW;
constexpr int SM_OMPHI = SM_PHI + 128;
constexpr int SM_CHI   = SM_OMPHI + 128;
constexpr int SM_OMCHI = SM_CHI + 128;
constexpr int SM_BETA  = SM_OMCHI + 128;
constexpr int SM_KAPPA = SM_BETA + 128;
constexpr int SM_INP   = SM_KAPPA + 128;        // 16 t x 8
constexpr int SM_PART  = SM_INP + 128;          // 4 col-groups x 64 rows
constexpr int SM_KH    = SM_PART + 256;         // 64
constexpr int SM_TOT   = SM_KH + 64;            // 22720 words
constexpr int SMEM_BYTES = SM_TOT * 4;          // 90,880 B  (2 CTAs/SM fit)

__device__ __forceinline__ void mma_bf16(float* c, const uint32_t* a, const uint32_t* b) {
    asm volatile(
        "mma.sync.aligned.m16n8k16.row.col.f32.bf16.bf16.f32 "
        "{%0,%1,%2,%3}, {%4,%5,%6,%7}, {%8,%9}, {%0,%1,%2,%3};\n"
        : "+f"(c[0]), "+f"(c[1]), "+f"(c[2]), "+f"(c[3])
        : "r"(a[0]), "r"(a[1]), "r"(a[2]), "r"(a[3]),
          "r"(b[0]), "r"(b[1]));
}

__device__ __forceinline__ uint32_t pack_bf2(float x, float y) {
    __nv_bfloat162 p = __floats2bfloat162_rn(x, y);
    return *(uint32_t*)&p;
}

__global__ __launch_bounds__(THREADS, 2)
void gql_kernel(const float* __restrict__ inp,       // (T,1,B,9)
                const float* __restrict__ phi_raw,   // (P,D)
                const float* __restrict__ chi_raw,
                const float* __restrict__ beta_raw,
                const float* __restrict__ kap_raw,
                const float* __restrict__ C_raw,     // (P,D,D)
                float* __restrict__ out)
{
    extern __shared__ float sm[];
    uint32_t* smu = (uint32_t*)sm;
    const int b    = blockIdx.x;
    const int tid  = threadIdx.x;
    const int lane = tid & 31;
    const int warp = tid >> 5;

    const int pid = (int)inp[b * 9 + 8];

    // ---------------- one-time parameter setup ----------------
    if (tid < 128) {
        const int d = tid;
        float pv = phi_raw[pid * 128 + d];
        float ph = 1.0f / (1.0f + expf(-pv));
        ph = fminf(fmaxf(ph, 0.01f), 0.99f);
        sm[SM_PHI + d]   = ph;
        sm[SM_OMPHI + d] = 1.0f - ph;

        float cv = chi_raw[pid * 128 + d];
        float ch = 1.0f / (1.0f + expf(-cv));
        ch = fminf(fmaxf(ch, 0.01f), 0.99f);
        sm[SM_CHI + d]   = ch;
        sm[SM_OMCHI + d] = 1.0f - ch;

        float bv = beta_raw[pid * 128 + d];
        float sp = (bv > 15.0f) ? bv : log1pf(expf(bv));
        sm[SM_BETA + d] = fminf(fmaxf(sp, 0.1f), 10.0f);

        float kv = kap_raw[pid * 128 + d];
        sm[SM_KAPPA + d] = fminf(fmaxf(kv, -10.0f), 10.0f);
    }

    // C[pid]: clip, pack k-pairs (d, d+1) as bf16x2; smem row = e, u32 col = d/2
    {
        const float* Cb = C_raw + (size_t)pid * (128 * 128);
        for (int idx = tid; idx < 64 * 128; idx += THREADS) {
            int e  = idx & 127;
            int dp = idx >> 7;            // 0..63
            float v0 = fminf(fmaxf(Cb[(2 * dp)     * 128 + e], -10.0f), 10.0f);
            float v1 = fminf(fmaxf(Cb[(2 * dp + 1) * 128 + e], -10.0f), 10.0f);
            smu[SM_BH + e * HROW + dp] = pack_bf2(v0, v1);
        }
    }
    __syncthreads();

    // warp tile: 32 rows x 32 cols. wm in {0,1}, wn in {0..3}
    const int wm  = warp >> 2;
    const int wn  = warp & 3;
    const int grp = lane >> 2;   // 0..7
    const int qd  = lane & 3;    // 0..3

    // ---- hoist B fragments for K16-steps 0..3 (32 regs); 4..7 read from SMEM ----
    uint32_t bf[4][4][2];
#pragma unroll
    for (int k = 0; k < 4; k++) {
#pragma unroll
        for (int j = 0; j < 4; j++) {
            const uint32_t* base = &smu[SM_BH + (wn * 32 + j * 8 + grp) * HROW + k * 8 + qd];
            bf[k][j][0] = base[0];
            bf[k][j][1] = base[4];
        }
    }

    // ---------------- per-thread scan state: owns (a, d0) and (a, d0+1) ----
    const int e0    = tid * 2;
    const int a_own = e0 >> 7;
    const int d0    = e0 & 127;

    const float phi0 = sm[SM_PHI + d0],   phi1 = sm[SM_PHI + d0 + 1];
    const float omp0 = sm[SM_OMPHI + d0], omp1 = sm[SM_OMPHI + d0 + 1];
    const float chi0 = sm[SM_CHI + d0],   chi1 = sm[SM_CHI + d0 + 1];
    const float omc0 = sm[SM_OMCHI + d0], omc1 = sm[SM_OMCHI + d0 + 1];

    float q0 = 0.5f, q1 = 0.5f, h0 = 0.0f, h1 = 0.0f;

    for (int c = 0; c < NCHUNK; c++) {
        const int tb = c * CHUNK;

        // ---- stage 1: load chunk inputs (16 t x 8) ----
        if (tid < 128) {
            int t = tid >> 3, cc = tid & 7;
            float v = inp[((size_t)(tb + t) * B_DIM + b) * 9 + cc];
            if (v != v) v = 0.0f;   // nan_to_num
            sm[SM_INP + tid] = v;
        }
        __syncthreads();

        // ---- stage 2: EMA scan -> H (bf16x2) + Q (fp32) tiles ----
#pragma unroll
        for (int t = 0; t < CHUNK; t++) {
            float av = sm[SM_INP + t * 8 + a_own];
            float rv = sm[SM_INP + t * 8 + 4 + a_own];
            float drive = rv * av;
            q0 = fmaf(phi0, drive, omp0 * q0);
            q1 = fmaf(phi1, drive, omp1 * q1);
            h0 = fmaf(chi0, av, omc0 * h0);
            h1 = fmaf(chi1, av, omc1 * h1);
            int row = t * 4 + a_own;
            smu[SM_AH + row * HROW + (d0 >> 1)] = pack_bf2(h0, h1);
            *(float2*)&sm[SM_Q + row * QROW + d0] = make_float2(q0, q1);
        }
        __syncthreads();

        // ---- stage 3: P = H * C (bf16 m16n8k16), warp tile 32x32 ----
        float acc[2][4][4];
#pragma unroll
        for (int i = 0; i < 2; i++)
#pragma unroll
            for (int j = 0; j < 4; j++)
#pragma unroll
                for (int r = 0; r < 4; r++) acc[i][j][r] = 0.0f;

#pragma unroll
        for (int k = 0; k < 8; k++) {
            uint32_t af[2][4];
#pragma unroll
            for (int i = 0; i < 2; i++) {
                const int r0 = wm * 32 + i * 16 + grp;
                const uint32_t* p0 = &smu[SM_AH + r0 * HROW + k * 8 + qd];
                const uint32_t* p1 = &smu[SM_AH + (r0 + 8) * HROW + k * 8 + qd];
                af[i][0] = p0[0];
                af[i][1] = p1[0];
                af[i][2] = p0[4];
                af[i][3] = p1[4];
            }
            if (k < 4) {
#pragma unroll
                for (int i = 0; i < 2; i++)
#pragma unroll
                    for (int j = 0; j < 4; j++)
                        mma_bf16(acc[i][j], af[i], bf[k][j]);
            } else {
                uint32_t bt[4][2];
#pragma unroll
                for (int j = 0; j < 4; j++) {
                    const uint32_t* base = &smu[SM_BH + (wn * 32 + j * 8 + grp) * HROW + k * 8 + qd];
                    bt[j][0] = base[0];
                    bt[j][1] = base[4];
                }
#pragma unroll
                for (int i = 0; i < 2; i++)
#pragma unroll
                    for (int j = 0; j < 4; j++)
                        mma_bf16(acc[i][j], af[i], bt[j]);
            }
        }

        // ---- kappa . h (bf16 H, fp32 kappa + accumulate); 2 threads per row ----
        if (tid < 128) {
            int row = tid >> 1, half = tid & 1;
            float kh = 0.0f;
            const uint4* hv = (const uint4*)&smu[SM_AH + row * HROW + half * 32];
            const float4* kv = (const float4*)&sm[SM_KAPPA + half * 64];
#pragma unroll
            for (int m = 0; m < 8; m++) {
                uint4 w = hv[m];
                float2 p0 = __bfloat1622float2(*(__nv_bfloat162*)&w.x);
                float2 p1 = __bfloat1622float2(*(__nv_bfloat162*)&w.y);
                float2 p2 = __bfloat1622float2(*(__nv_bfloat162*)&w.z);
                float2 p3 = __bfloat1622float2(*(__nv_bfloat162*)&w.w);
                float4 k0 = kv[2 * m], k1 = kv[2 * m + 1];
                kh += p0.x * k0.x + p0.y * k0.y + p1.x * k0.z + p1.y * k0.w
                    + p2.x * k1.x + p2.y * k1.y + p3.x * k1.z + p3.y * k1.w;
            }
            kh += __shfl_xor_sync(0xFFFFFFFFu, kh, 1);
            if (half == 0) sm[SM_KH + row] = kh;
        }

        // ---- epilogue: rowdot((P + beta^T), Q) -> PART[wn][row] ----
#pragma unroll
        for (int i = 0; i < 2; i++) {
            float part0 = 0.0f, part1 = 0.0f;
            const int r0 = wm * 32 + i * 16 + grp;
            const int r1 = r0 + 8;
#pragma unroll
            for (int j = 0; j < 4; j++) {
                const int col = wn * 32 + j * 8 + qd * 2;
                const float b0 = sm[SM_BETA + col];
                const float b1 = sm[SM_BETA + col + 1];
                float2 qv0 = *(const float2*)&sm[SM_Q + r0 * QROW + col];
                float2 qv1 = *(const float2*)&sm[SM_Q + r1 * QROW + col];
                part0 += (acc[i][j][0] + b0) * qv0.x + (acc[i][j][1] + b1) * qv0.y;
                part1 += (acc[i][j][2] + b0) * qv1.x + (acc[i][j][3] + b1) * qv1.y;
            }
            part0 += __shfl_xor_sync(0xFFFFFFFFu, part0, 1);
            part0 += __shfl_xor_sync(0xFFFFFFFFu, part0, 2);
            part1 += __shfl_xor_sync(0xFFFFFFFFu, part1, 1);
            part1 += __shfl_xor_sync(0xFFFFFFFFu, part1, 2);
            if (qd == 0) {
                sm[SM_PART + wn * 64 + r0] = part0;
                sm[SM_PART + wn * 64 + r1] = part1;
            }
        }
        __syncthreads();

        // ---- stage 5: combine col-groups + kappa.h, write logits (T,1,B,A) ----
        if (tid < 64) {
            float l = sm[SM_PART + tid] + sm[SM_PART + 64 + tid]
                    + sm[SM_PART + 128 + tid] + sm[SM_PART + 192 + tid]
                    + sm[SM_KH + tid];
            int t = tb + (tid >> 2);
            int a = tid & 3;
            out[(size_t)t * (B_DIM * A_DIM) + b * A_DIM + a] = l;
        }
        __syncthreads();
    }

    // ---- final states: q (B,A,D) then h (B,A,D), exact fp32 ----
    *(float2*)&out[OUT_Q + (size_t)b * 512 + e0] = make_float2(q0, q1);
    *(float2*)&out[OUT_H + (size_t)b * 512 + e0] = make_float2(h0, h1);
}

extern "C" void kernel_launch(void* const* d_in, const int* in_sizes, int n_in,
                              void* d_out, int out_size) {
    const float* inp      = (const float*)d_in[0];
    const float* phi_raw  = (const float*)d_in[1];
    const float* chi_raw  = (const float*)d_in[2];
    const float* beta_raw = (const float*)d_in[3];
    const float* kap_raw  = (const float*)d_in[4];
    const float* C_raw    = (const float*)d_in[5];
    float* out = (float*)d_out;

    cudaFuncSetAttribute(gql_kernel, cudaFuncAttributeMaxDynamicSharedMemorySize, SMEM_BYTES);
    gql_kernel<<<B_DIM, THREADS, SMEM_BYTES>>>(inp, phi_raw, chi_raw, beta_raw,
                                               kap_raw, C_raw, out);
}